// round 11
// baseline (speedup 1.0000x reference)
#include <cuda_runtime.h>
#include <cstdint>

#define BATCH   32
#define CIN     64
#define COUT    64
#define HH      64
#define WW      64
#define HOUT    62
#define WOUT    62
#define KTOT    576          // CIN * 3 * 3
#define BLOCK   128
#define KCHUNK  32
#define NCHUNK  18           // 576 / 32
#define WT      68           // w_t row stride: 68 % 32 == 4 (swizzle algebra), 16B-aligned

typedef unsigned long long u64;

// persistent scratch: features transposed to [cin][h][w][batch] (batch contiguous)
__device__ float g_xposed[CIN * HH * WW * BATCH];   // 33.5 MB

__device__ __forceinline__ u64 pk(float lo, float hi) {
    u64 r;
    asm("mov.b64 %0, {%1, %2};" : "=l"(r) : "f"(lo), "f"(hi));
    return r;
}
__device__ __forceinline__ void upk(u64 v, float& lo, float& hi) {
    asm("mov.b64 {%0, %1}, %2;" : "=f"(lo), "=f"(hi) : "l"(v));
}
// Packed dual-FMA on the Blackwell f32x2 pipe (2x FFMA rate)
__device__ __forceinline__ void fma2(u64& d, u64 a, u64 b) {
    asm("fma.rn.f32x2 %0, %1, %2, %0;" : "+l"(d) : "l"(a), "l"(b));
}
__device__ __forceinline__ void cp16(uint32_t dst, const float* src) {
    asm volatile("cp.async.cg.shared.global [%0], [%1], 16;" :: "r"(dst), "l"(src) : "memory");
}
__device__ __forceinline__ void cpcommit() {
    asm volatile("cp.async.commit_group;" ::: "memory");
}
__device__ __forceinline__ void cpwait0() {
    asm volatile("cp.async.wait_group 0;" ::: "memory");
}

// ---------------- kernel 1: transpose features [b][cin][h][w] -> [cin][h][w][b] ----
__global__ void __launch_bounds__(256)
xpose_kernel(const float* __restrict__ features)
{
    __shared__ float t[32][33];
    const int cin = blockIdx.x >> 6;
    const int hh  = blockIdx.x & 63;
    const int ww0 = blockIdx.y << 5;
    const int tx = threadIdx.x & 31;
    const int ty = threadIdx.x >> 5;   // 0..7

    #pragma unroll
    for (int i = 0; i < 4; i++) {
        int b = ty + 8 * i;
        t[b][tx] = features[((b * CIN + cin) * HH + hh) * WW + ww0 + tx];
    }
    __syncthreads();
    #pragma unroll
    for (int i = 0; i < 4; i++) {
        int wwi = ty + 8 * i;
        g_xposed[((cin * HH + hh) * WW + ww0 + wwi) * BATCH + tx] = t[tx][wwi];
    }
}

// ---------------- kernel 2: locally-connected GEMM, 1 location per CTA --------------
__global__ void __launch_bounds__(BLOCK, 6)
lc2d_kernel(const float* __restrict__ weights,
            const float* __restrict__ bias,
            float* __restrict__ out)
{
    // 25.4 KB static smem -> ~7 CTAs/SM (28 warps)
    __shared__ float x_s[2][KCHUNK][BATCH];   // 8 KB
    __shared__ float w_s[2][KCHUNK][WT];      // 17.4 KB, k-major + XOR swizzle

    const int tid = threadIdx.x;
    const int w   = blockIdx.x;
    const int h   = blockIdx.y;

    // compute mapping: bg = batch pair (2bg, 2bg+1); cq = couts 8cq..8cq+7
    const int bg = tid & 15;
    const int cq = tid >> 4;                  // 0..7 (2 distinct per warp -> broadcast LDS)

    // w-loader mapping: 4 rows (c = cb + 16u), one 16B k-segment (qq)
    const int qq = tid & 7;
    const int cb = tid >> 3;                  // 0..15

    const float* wloc  = weights + (size_t)(h * WOUT + w) * (COUT * KTOT);
    const float* fbase = g_xposed + (size_t)(h * WW + w) * BATCH;

    float4 rel[4];   // w register relay (one chunk ahead of smem)

    auto ldg_w = [&](int ch) {
        const float* src = wloc + ch * KCHUNK + qq * 4;
        #pragma unroll
        for (int u = 0; u < 4; u++)
            rel[u] = *(const float4*)(src + (size_t)(cb + 16 * u) * KTOT);
    };
    // k-major store, swizzle col = c ^ ((kk>>2)<<2): conflict-free (verified algebra)
    auto sts_w = [&](int buf) {
        #pragma unroll
        for (int u = 0; u < 4; u++) {
            const int c = cb + 16 * u;
            const float* v = &rel[u].x;
            #pragma unroll
            for (int e = 0; e < 4; e++) {
                const int kk = qq * 4 + e;
                w_s[buf][kk][c ^ ((kk >> 2) << 2)] = v[e];
            }
        }
    };
    // x gather: 2 coalesced 16B cp.async per thread
    auto issue_x = [&](int ch, int slot) {
        #pragma unroll
        for (int s = 0; s < 2; s++) {
            const int idx = tid + s * BLOCK;        // 0..255
            const int k   = idx >> 3;
            const int seg = idx & 7;
            const int r   = ch * KCHUNK + k;
            const int cin = r / 9;
            const int f   = r - cin * 9;
            const int ii  = f / 3;
            const int jj  = f - ii * 3;
            const float* src = fbase + ((size_t)cin * (HH * WW) + ii * WW + jj) * BATCH
                             + seg * 4;
            uint32_t dst = (uint32_t)__cvta_generic_to_shared(&x_s[slot][k][seg * 4]);
            cp16(dst, src);
        }
        cpcommit();
    };

    // ---- prologue ----
    ldg_w(0);
    issue_x(0, 0);
    sts_w(0);
    ldg_w(1);

    u64 acc[2][4];   // [batch p][cout-pair j]
    #pragma unroll
    for (int p = 0; p < 2; p++)
        #pragma unroll
        for (int j = 0; j < 4; j++) acc[p][j] = 0ULL;

    #pragma unroll 1
    for (int ch = 0; ch < NCHUNK; ch++) {
        cpwait0();            // every thread's x(ch) ops complete
        __syncthreads();      // all threads' x(ch)+w(ch) published; old slot/buf free

        if (ch + 1 < NCHUNK) {
            sts_w((ch + 1) & 1);               // consume rel = w(ch+1)
            if (ch + 2 < NCHUNK) ldg_w(ch + 2);
            issue_x(ch + 1, (ch + 1) & 1);     // overlaps with compute below
        }

        const float* xb = &x_s[ch & 1][0][bg * 2];
        const float* wb = &w_s[ch & 1][0][0];

        #pragma unroll
        for (int kk = 0; kk < KCHUNK; kk++) {
            const int swz = (kk >> 2) << 2;
            // 2 batches: one LDS.64 (16 distinct 8B addrs = 128B, 1 wf)
            u64 xv = *(const u64*)(xb + kk * BATCH);
            float x0, x1;
            upk(xv, x0, x1);                    // register aliasing (free-ish)
            u64 xd0 = pk(x0, x0), xd1 = pk(x1, x1);
            // 8 couts as 4 packed pairs: two LDS.128 (2 distinct addrs, broadcast)
            ulonglong2 wa = *(const ulonglong2*)(wb + kk * WT + ((cq * 8    ) ^ swz));
            ulonglong2 wd = *(const ulonglong2*)(wb + kk * WT + ((cq * 8 + 4) ^ swz));

            fma2(acc[0][0], xd0, wa.x); fma2(acc[1][0], xd1, wa.x);
            fma2(acc[0][1], xd0, wa.y); fma2(acc[1][1], xd1, wa.y);
            fma2(acc[0][2], xd0, wd.x); fma2(acc[1][2], xd1, wd.x);
            fma2(acc[0][3], xd0, wd.y); fma2(acc[1][3], xd1, wd.y);
        }
    }

    // ---- epilogue: unpack cout pairs, add bias, scattered STG.32 ----
    const float* bl = bias + (h * WOUT + w) * COUT + cq * 8;

    #pragma unroll
    for (int p = 0; p < 2; p++) {
        const int b = bg * 2 + p;
        #pragma unroll
        for (int j = 0; j < 4; j++) {
            const int c = cq * 8 + 2 * j;
            float lo, hi;
            upk(acc[p][j], lo, hi);
            out[((b * COUT + c    ) * HOUT + h) * WOUT + w] = lo + bl[2 * j];
            out[((b * COUT + c + 1) * HOUT + h) * WOUT + w] = hi + bl[2 * j + 1];
        }
    }
}

extern "C" void kernel_launch(void* const* d_in, const int* in_sizes, int n_in,
                              void* d_out, int out_size)
{
    const float* features = nullptr;
    const float* weights  = nullptr;
    const float* bias     = nullptr;
    for (int i = 0; i < n_in; i++) {
        if      (in_sizes[i] == BATCH * CIN * HH * WW)        features = (const float*)d_in[i];
        else if (in_sizes[i] == HOUT * WOUT * COUT * CIN * 9) weights  = (const float*)d_in[i];
        else if (in_sizes[i] == HOUT * WOUT * COUT)           bias     = (const float*)d_in[i];
    }
    float* out = (float*)d_out;

    // 1) transpose features -> [cin][h][w][batch]
    xpose_kernel<<<dim3(CIN * HH, WW / 32), 256>>>(features);
    // 2) main locally-connected GEMM (1 location per CTA, 28 warps/SM)
    lc2d_kernel<<<dim3(WOUT, HOUT), BLOCK>>>(weights, bias, out);
}

// round 12
// speedup vs baseline: 1.1049x; 1.1049x over previous
#include <cuda_runtime.h>
#include <cstdint>

#define BATCH   32
#define CIN     64
#define COUT    64
#define HH      64
#define WW      64
#define HOUT    62
#define WOUT    62
#define KTOT    576          // CIN * 3 * 3
#define BLOCK   128
#define KCHUNK  16
#define NCHUNK  36           // 576 / 16
#define WT      68           // w_t row stride: 16B-aligned, swizzle-friendly

typedef unsigned long long u64;

// persistent scratch: features transposed to [cin][h][w][batch] (batch contiguous)
__device__ float g_xposed[CIN * HH * WW * BATCH];   // 33.5 MB

// static smem: x[2][2][16][32] = 8 KB, w[2][2][16][68] = 17.4 KB -> 25.4 KB total

__device__ __forceinline__ u64 pk(float lo, float hi) {
    u64 r;
    asm("mov.b64 %0, {%1, %2};" : "=l"(r) : "f"(lo), "f"(hi));
    return r;
}
__device__ __forceinline__ void upk(u64 v, float& lo, float& hi) {
    asm("mov.b64 {%0, %1}, %2;" : "=f"(lo), "=f"(hi) : "l"(v));
}
// Packed dual-FMA on the Blackwell f32x2 pipe (2x FFMA rate)
__device__ __forceinline__ void fma2(u64& d, u64 a, u64 b) {
    asm("fma.rn.f32x2 %0, %1, %2, %0;" : "+l"(d) : "l"(a), "l"(b));
}
__device__ __forceinline__ void cp16(uint32_t dst, const float* src) {
    asm volatile("cp.async.cg.shared.global [%0], [%1], 16;" :: "r"(dst), "l"(src) : "memory");
}
__device__ __forceinline__ void cpcommit() {
    asm volatile("cp.async.commit_group;" ::: "memory");
}
__device__ __forceinline__ void cpwait0() {
    asm volatile("cp.async.wait_group 0;" ::: "memory");
}

// ---------------- kernel 1: transpose features [b][cin][h][w] -> [cin][h][w][b] ----
__global__ void __launch_bounds__(256)
xpose_kernel(const float* __restrict__ features)
{
    __shared__ float t[32][33];
    const int cin = blockIdx.x >> 6;
    const int hh  = blockIdx.x & 63;
    const int ww0 = blockIdx.y << 5;
    const int tx = threadIdx.x & 31;
    const int ty = threadIdx.x >> 5;   // 0..7

    #pragma unroll
    for (int i = 0; i < 4; i++) {
        int b = ty + 8 * i;
        t[b][tx] = features[((b * CIN + cin) * HH + hh) * WW + ww0 + tx];
    }
    __syncthreads();
    #pragma unroll
    for (int i = 0; i < 4; i++) {
        int wwi = ty + 8 * i;
        g_xposed[((cin * HH + hh) * WW + ww0 + wwi) * BATCH + tx] = t[tx][wwi];
    }
}

// ---------------- kernel 2: locally-connected GEMM, 2 w-locations per CTA -----------
// R8 thread tile (4 batches x 8 couts, 16 FFMA2 / 3 LDS-wf per k) + KCHUNK=16 to
// halve the weight relay (rel[4]) and smem, unlocking 5 CTAs/SM (20 warps).
__global__ void __launch_bounds__(BLOCK, 5)
lc2d_kernel(const float* __restrict__ weights,
            const float* __restrict__ bias,
            float* __restrict__ out)
{
    __shared__ float x_s[2][2][KCHUNK][BATCH];   // [slot][loc][kk][batch]
    __shared__ float w_s[2][2][KCHUNK][WT];      // [buf][loc][kk][col^swz]

    const int tid = threadIdx.x;
    const int h   = blockIdx.y;
    const int w0  = blockIdx.x * 2;         // locations (h, w0) and (h, w0+1)

    // compute mapping: loc = tid>>6; bg = batches bg*4..; cq = couts cq*8..
    const int loc = tid >> 6;
    const int t   = tid & 63;
    const int bg  = t & 7;
    const int cq  = t >> 3;                 // 0..7

    // w-loader mapping (per loc, 64 threads): 4 rows (c = cb+16u) x one 16B k-seg
    const int qq = t & 3;                   // k-segment 0..3 (4 floats each)
    const int cb = t >> 2;                  // 0..15

    const float* wloc  = weights + (size_t)(h * WOUT + w0 + loc) * (COUT * KTOT);
    const float* fbase = g_xposed + (size_t)(h * WW + w0) * BATCH;

    float4 rel[4];   // w register relay (one chunk ahead of smem)

    auto ldg_w = [&](int ch) {
        const float* src = wloc + ch * KCHUNK + qq * 4;
        #pragma unroll
        for (int u = 0; u < 4; u++)
            rel[u] = *(const float4*)(src + (size_t)(cb + 16 * u) * KTOT);
    };
    // k-major store, swizzle col = c ^ ((kk>>2)<<2): STS conflict-free
    // (banks (16qq + (cb^4qq) + 16u + 4e) mod 32 enumerate all 32 lanes)
    auto sts_w = [&](int buf) {
        #pragma unroll
        for (int u = 0; u < 4; u++) {
            const int c = cb + 16 * u;
            const float* v = &rel[u].x;
            #pragma unroll
            for (int e = 0; e < 4; e++) {
                const int kk = qq * 4 + e;
                w_s[buf][loc][kk][c ^ ((kk >> 2) << 2)] = v[e];
            }
        }
    };
    // x gather: 2 coalesced 16B cp.async per thread (both locations)
    auto issue_x = [&](int ch, int slot) {
        #pragma unroll
        for (int s = 0; s < 2; s++) {
            const int idx = tid + s * BLOCK;        // 0..255
            const int l   = idx >> 7;
            const int rem = idx & 127;
            const int k   = rem >> 3;               // 0..15
            const int seg = rem & 7;
            const int r   = ch * KCHUNK + k;
            const int cin = r / 9;
            const int f   = r - cin * 9;
            const int ii  = f / 3;
            const int jj  = f - ii * 3;
            const float* src = fbase + ((size_t)cin * (HH * WW)
                             + ii * WW + l + jj) * BATCH + seg * 4;
            uint32_t dst = (uint32_t)__cvta_generic_to_shared(&x_s[slot][l][k][seg * 4]);
            cp16(dst, src);
        }
        cpcommit();
    };

    // ---- prologue ----
    ldg_w(0);
    issue_x(0, 0);
    sts_w(0);
    ldg_w(1);

    u64 acc[4][4];   // [batch b][cout-pair j]
    #pragma unroll
    for (int p = 0; p < 4; p++)
        #pragma unroll
        for (int j = 0; j < 4; j++) acc[p][j] = 0ULL;

    #pragma unroll 1
    for (int ch = 0; ch < NCHUNK; ch++) {
        cpwait0();            // x(ch) landed (issued last iter / prologue)
        __syncthreads();      // publish x(ch), w(ch); old slot/buf now free

        if (ch + 1 < NCHUNK) {
            sts_w((ch + 1) & 1);               // consume rel = w(ch+1)
            if (ch + 2 < NCHUNK) ldg_w(ch + 2);
            issue_x(ch + 1, (ch + 1) & 1);     // overlaps with compute below
        }

        const float* xb = &x_s[ch & 1][loc][0][bg * 4];
        const float* wb = &w_s[ch & 1][loc][0][0];

        #pragma unroll
        for (int kk = 0; kk < KCHUNK; kk++) {
            const int swz = (kk >> 2) << 2;
            // 4 batches: one LDS.128 (8 distinct 16B addrs, 1 wf)
            ulonglong2 xv = *(const ulonglong2*)(xb + kk * BATCH);
            float x0, x1, x2, x3;
            upk(xv.x, x0, x1);
            upk(xv.y, x2, x3);
            u64 xd0 = pk(x0, x0), xd1 = pk(x1, x1);
            u64 xd2 = pk(x2, x2), xd3 = pk(x3, x3);
            // 8 couts as 4 packed pairs: two LDS.128 (4 distinct addrs, broadcast)
            ulonglong2 wa = *(const ulonglong2*)(wb + kk * WT + ((cq * 8    ) ^ swz));
            ulonglong2 wd = *(const ulonglong2*)(wb + kk * WT + ((cq * 8 + 4) ^ swz));

            fma2(acc[0][0], xd0, wa.x); fma2(acc[1][0], xd1, wa.x);
            fma2(acc[2][0], xd2, wa.x); fma2(acc[3][0], xd3, wa.x);
            fma2(acc[0][1], xd0, wa.y); fma2(acc[1][1], xd1, wa.y);
            fma2(acc[2][1], xd2, wa.y); fma2(acc[3][1], xd3, wa.y);
            fma2(acc[0][2], xd0, wd.x); fma2(acc[1][2], xd1, wd.x);
            fma2(acc[2][2], xd2, wd.x); fma2(acc[3][2], xd3, wd.x);
            fma2(acc[0][3], xd0, wd.y); fma2(acc[1][3], xd1, wd.y);
            fma2(acc[2][3], xd2, wd.y); fma2(acc[3][3], xd3, wd.y);
        }
    }

    // ---- epilogue: unpack cout pairs, add bias, scattered STG.32 ----
    const int wabs = w0 + loc;
    const float* bl = bias + (h * WOUT + wabs) * COUT + cq * 8;

    #pragma unroll
    for (int p = 0; p < 4; p++) {
        const int b = bg * 4 + p;
        #pragma unroll
        for (int j = 0; j < 4; j++) {
            const int c = cq * 8 + 2 * j;
            float lo, hi;
            upk(acc[p][j], lo, hi);
            out[((b * COUT + c    ) * HOUT + h) * WOUT + wabs] = lo + bl[2 * j];
            out[((b * COUT + c + 1) * HOUT + h) * WOUT + wabs] = hi + bl[2 * j + 1];
        }
    }
}

extern "C" void kernel_launch(void* const* d_in, const int* in_sizes, int n_in,
                              void* d_out, int out_size)
{
    const float* features = nullptr;
    const float* weights  = nullptr;
    const float* bias     = nullptr;
    for (int i = 0; i < n_in; i++) {
        if      (in_sizes[i] == BATCH * CIN * HH * WW)        features = (const float*)d_in[i];
        else if (in_sizes[i] == HOUT * WOUT * COUT * CIN * 9) weights  = (const float*)d_in[i];
        else if (in_sizes[i] == HOUT * WOUT * COUT)           bias     = (const float*)d_in[i];
    }
    float* out = (float*)d_out;

    // 1) transpose features -> [cin][h][w][batch]
    xpose_kernel<<<dim3(CIN * HH, WW / 32), 256>>>(features);
    // 2) main locally-connected GEMM (2 locations per CTA, 20 warps/SM)
    lc2d_kernel<<<dim3(WOUT / 2, HOUT), BLOCK>>>(weights, bias, out);
}